// round 14
// baseline (speedup 1.0000x reference)
#include <cuda_runtime.h>
#include <cuda_fp16.h>
#include <mma.h>
#include <math.h>
#include <cstdint>

using namespace nvcuda;

#define LSEQ 32768
#define CDIM 512
#define SCH 128
#define NCHUNK (LSEQ / SCH)   // 256
#define EPS 1e-5f

// GEMM tiling: block 128x256, 8 warps (256 thr), warp tile 64x64, BK=64, fp16, 3 stages
#define GTHREADS 256
#define NSTAGE 3
#define AS_STRIDE 72            // 64 + 8 pad -> 144B rows (odd multiple of 16B: conflict-free)
#define BS_STRIDE 264           // 256 + 8 pad -> 528B rows (odd multiple of 16B)
#define EP_STRIDE 132
#define A_BYTES (128 * AS_STRIDE * 2)          // 18432
#define B_BYTES (64 * BS_STRIDE * 2)           // 33792
#define STG_BYTES (A_BYTES + B_BYTES)          // 52224
#define SMEM_TOTAL (NSTAGE * STG_BYTES)        // 156672 (>= 128*132*4 = 67584 epilogue)

// ---------------- scratch (static device globals; no allocation) ----------------
__device__ __half g_hidden[LSEQ * CDIM];
__device__ __half g_u[LSEQ * CDIM];
__device__ __half g_gate[LSEQ * CDIM];
__device__ __half g_state[LSEQ * CDIM];
__device__ float  g_x2[LSEQ * CDIM];
__device__ __half g_h[LSEQ * CDIM];
__device__ __half g_ff[LSEQ * 2 * CDIM];
__device__ __half g_tmp[LSEQ * CDIM];     // fwd-scan scratch (fp16)
__device__ float  g_decay[CDIM];
__device__ float  g_fend[NCHUNK * CDIM];
__device__ float  g_bend[NCHUNK * CDIM];
__device__ float  g_fcar[NCHUNK * CDIM];
__device__ float  g_bcar[NCHUNK * CDIM];
// fp16 weight copies: W_in | W_gate | W_out | W_ff1 | W_ff2
__device__ __half g_wt[3 * CDIM * CDIM + 2 * CDIM * 2 * CDIM];

__device__ __forceinline__ uint32_t smem_u32(const void* p) {
    uint32_t a;
    asm("{ .reg .u64 t; cvta.to.shared.u64 t, %1; cvt.u32.u64 %0, t; }" : "=r"(a) : "l"(p));
    return a;
}

#define CP_ASYNC16(dst_u32, gptr) \
    asm volatile("cp.async.cg.shared.global [%0], [%1], 16;" :: "r"(dst_u32), "l"(gptr))
#define CP_COMMIT() asm volatile("cp.async.commit_group;" ::: "memory")
#define CP_WAIT(n)  asm volatile("cp.async.wait_group %0;" :: "n"(n) : "memory")

// ---------------- weight packing (2 launches total) ----------------
__global__ void pack_w1(const float* __restrict__ Win, const float* __restrict__ Wgate,
                        const float* __restrict__ Wout, __half* __restrict__ wt) {
    int i = blockIdx.x * blockDim.x + threadIdx.x;     // 0..196607 float4 units
    int seg = i >> 16;
    int o = i & 65535;
    const float* src = (seg == 0) ? Win : (seg == 1) ? Wgate : Wout;
    float4 v = ((const float4*)src)[o];
    __half2* d2 = (__half2*)wt + (size_t)i * 2;
    d2[0] = __floats2half2_rn(v.x, v.y);
    d2[1] = __floats2half2_rn(v.z, v.w);
}

__global__ void pack_w2(const float* __restrict__ Wff1, const float* __restrict__ Wff2,
                        const float* __restrict__ logit,
                        __half* __restrict__ wt2, float* __restrict__ decay) {
    int i = blockIdx.x * blockDim.x + threadIdx.x;
    if (i < 262144) {
        const float* src = (i < 131072) ? Wff1 : Wff2;
        int o = (i < 131072) ? i : i - 131072;
        float4 v = ((const float4*)src)[o];
        __half2* d2 = (__half2*)wt2 + (size_t)i * 2;
        d2[0] = __floats2half2_rn(v.x, v.y);
        d2[1] = __floats2half2_rn(v.z, v.w);
    } else {
        int j = i - 262144;
        if (j < CDIM) decay[j] = 1.0f / (1.0f + expf(-logit[j]));
    }
}

// ---------------- LayerNorm: one warp per row; fp16 output ----------------
__global__ void ln_kernel(const float* __restrict__ x, const float* __restrict__ w,
                          const float* __restrict__ b, __half* __restrict__ out) {
    int row = blockIdx.x * blockDim.y + threadIdx.y;
    int lane = threadIdx.x;
    const float4* xr = (const float4*)(x + (size_t)row * CDIM);
    float4 v[4];
    float s = 0.f, ss = 0.f;
#pragma unroll
    for (int i = 0; i < 4; i++) {
        v[i] = xr[lane + i * 32];
        s += v[i].x + v[i].y + v[i].z + v[i].w;
        ss += v[i].x * v[i].x + v[i].y * v[i].y + v[i].z * v[i].z + v[i].w * v[i].w;
    }
#pragma unroll
    for (int off = 16; off > 0; off >>= 1) {
        s += __shfl_xor_sync(0xFFFFFFFFu, s, off);
        ss += __shfl_xor_sync(0xFFFFFFFFu, ss, off);
    }
    float mu = s * (1.0f / CDIM);
    float var = ss * (1.0f / CDIM) - mu * mu;
    float rstd = rsqrtf(var + EPS);
    const float4* w4 = (const float4*)w;
    const float4* b4 = (const float4*)b;
    __half2* o2 = (__half2*)(out + (size_t)row * CDIM);
#pragma unroll
    for (int i = 0; i < 4; i++) {
        int idx = lane + i * 32;
        float4 wv = w4[idx], bv = b4[idx];
        float ox = (v[i].x - mu) * rstd * wv.x + bv.x;
        float oy = (v[i].y - mu) * rstd * wv.y + bv.y;
        float oz = (v[i].z - mu) * rstd * wv.z + bv.z;
        float ow = (v[i].w - mu) * rstd * wv.w + bv.w;
        o2[idx * 2]     = __floats2half2_rn(ox, oy);
        o2[idx * 2 + 1] = __floats2half2_rn(oz, ow);
    }
}

// ---------------- fp16 wmma GEMM 128x256, 8 warps (64x64 tiles), BK=64, 3-stage ----------------
// A: MxK fp16 row-major, B: KxN fp16 row-major. C = epi(A@B + bias) [+ res].
// EPI: 0 = identity, 1 = sigmoid, 2 = silu.  OH16: output fp16 (else fp32).
template <int EPI, bool OH16>
__global__ void __launch_bounds__(GTHREADS, 1)
gemm_kernel(const __half* __restrict__ A, const __half* __restrict__ B,
            const float* __restrict__ bias, const float* __restrict__ res,
            void* __restrict__ Cout, int M, int N, int K) {
    extern __shared__ char smem[];
    uint32_t sb = smem_u32(smem);

    int tid = threadIdx.x;
    int w = tid >> 5;
    int wr = w & 1;        // 0..1  -> 64-row slab
    int wc = w >> 1;       // 0..3  -> 64-col slab
    int rowBase = blockIdx.y * 128;
    int nBase = blockIdx.x * 256;

    wmma::fragment<wmma::accumulator, 16, 16, 16, float> acc[4][4];
#pragma unroll
    for (int i = 0; i < 4; i++)
#pragma unroll
        for (int j = 0; j < 4; j++) wmma::fill_fragment(acc[i][j], 0.0f);

    const int T = K >> 6;   // BK = 64

    // A tile 128x64 fp16 (stride 72), B tile 64x256 fp16 (stride 264)
    auto load_stage = [&](int t, int s) {
        int k0 = t << 6;
        uint32_t abase = sb + s * STG_BYTES;
        uint32_t bbase = abase + A_BYTES;
#pragma unroll
        for (int p = 0; p < 4; p++) {
            int idx = tid + GTHREADS * p;      // 1024 chunks of 8 fp16
            int row = idx >> 3;
            int c8 = (idx & 7) * 8;
            CP_ASYNC16(abase + (uint32_t)(row * AS_STRIDE + c8) * 2,
                       A + (size_t)(rowBase + row) * K + k0 + c8);
        }
#pragma unroll
        for (int p = 0; p < 8; p++) {
            int idx = tid + GTHREADS * p;      // 2048 chunks
            int kr = idx >> 5;
            int c8 = (idx & 31) * 8;
            CP_ASYNC16(bbase + (uint32_t)(kr * BS_STRIDE + c8) * 2,
                       B + (size_t)(k0 + kr) * N + nBase + c8);
        }
    };

    // prologue: stages 0, 1
#pragma unroll
    for (int s = 0; s < NSTAGE - 1; s++) {
        load_stage(s, s);
        CP_COMMIT();
    }

    for (int t = 0; t < T; t++) {
        CP_WAIT(NSTAGE - 2);
        __syncthreads();
        // slot (t+2)%3 == (t-1)%3: sync above proves all warps finished compute t-1
        if (t + NSTAGE - 1 < T) load_stage(t + NSTAGE - 1, (t + NSTAGE - 1) % NSTAGE);
        CP_COMMIT();   // unconditional: exact group accounting

        int s = t % NSTAGE;
        const __half* As = (const __half*)(smem + s * STG_BYTES);
        const __half* Bs = (const __half*)(smem + s * STG_BYTES + A_BYTES);
#pragma unroll
        for (int kk = 0; kk < 4; kk++) {
            wmma::fragment<wmma::matrix_a, 16, 16, 16, __half, wmma::row_major> a[4];
            wmma::fragment<wmma::matrix_b, 16, 16, 16, __half, wmma::row_major> bfr[4];
#pragma unroll
            for (int i = 0; i < 4; i++)
                wmma::load_matrix_sync(a[i], As + (wr * 64 + i * 16) * AS_STRIDE + kk * 16, AS_STRIDE);
#pragma unroll
            for (int j = 0; j < 4; j++)
                wmma::load_matrix_sync(bfr[j], Bs + (kk * 16) * BS_STRIDE + wc * 64 + j * 16, BS_STRIDE);
#pragma unroll
            for (int i = 0; i < 4; i++)
#pragma unroll
                for (int j = 0; j < 4; j++)
                    wmma::mma_sync(acc[i][j], a[i], bfr[j], acc[i][j]);
        }
    }
    __syncthreads();   // all compute done before smem reuse

    // ---- epilogue: two 128-col halves via reused smem staging ----
    float* ep = (float*)smem;
#pragma unroll
    for (int h = 0; h < 2; h++) {
        if ((wc >> 1) == h) {
            int cbase = (wc & 1) * 64;
#pragma unroll
            for (int i = 0; i < 4; i++)
#pragma unroll
                for (int j = 0; j < 4; j++)
                    wmma::store_matrix_sync(ep + (size_t)(wr * 64 + i * 16) * EP_STRIDE + cbase + j * 16,
                                            acc[i][j], EP_STRIDE, wmma::mem_row_major);
        }
        __syncthreads();

        int gc0 = nBase + h * 128;
#pragma unroll
        for (int p = 0; p < 16; p++) {
            int idx = tid + GTHREADS * p;     // 4096 float4 = 128 rows x 32 float4
            int row = idx >> 5;
            int c4 = (idx & 31) * 4;
            float4 v = *(float4*)(ep + (size_t)row * EP_STRIDE + c4);
            float4 bv = *(const float4*)(bias + gc0 + c4);
            v.x += bv.x; v.y += bv.y; v.z += bv.z; v.w += bv.w;
            if (EPI == 1) {
                v.x = 1.0f / (1.0f + expf(-v.x)); v.y = 1.0f / (1.0f + expf(-v.y));
                v.z = 1.0f / (1.0f + expf(-v.z)); v.w = 1.0f / (1.0f + expf(-v.w));
            }
            if (EPI == 2) {
                v.x = v.x / (1.0f + expf(-v.x)); v.y = v.y / (1.0f + expf(-v.y));
                v.z = v.z / (1.0f + expf(-v.z)); v.w = v.w / (1.0f + expf(-v.w));
            }
            size_t goff = (size_t)(rowBase + row) * N + gc0 + c4;
            if (res) {
                float4 rv = *(const float4*)(res + goff);
                v.x += rv.x; v.y += rv.y; v.z += rv.z; v.w += rv.w;
            }
            if (OH16) {
                __half2* op = (__half2*)((__half*)Cout + goff);
                op[0] = __floats2half2_rn(v.x, v.y);
                op[1] = __floats2half2_rn(v.z, v.w);
            } else {
                *(float4*)((float*)Cout + goff) = v;
            }
        }
        __syncthreads();
    }
}

// ---------------- chunked bidirectional scan (fp16 inputs, fp32 accumulation) ----------------
__global__ void scan_pass1(const __half* __restrict__ u, const float* __restrict__ decay,
                           float* __restrict__ fend, float* __restrict__ bend) {
    int c = threadIdx.x;
    int ch = blockIdx.x;
    float d = decay[c];
    const __half* up = u + (size_t)ch * SCH * CDIM + c;
    float acc = 0.f;
#pragma unroll 8
    for (int r = 0; r < SCH; r++) acc = fmaf(d, acc, __half2float(up[r * CDIM]));
    fend[ch * CDIM + c] = acc;
    acc = 0.f;
#pragma unroll 8
    for (int r = SCH - 1; r >= 0; r--) acc = fmaf(d, acc, __half2float(up[r * CDIM]));
    bend[ch * CDIM + c] = acc;
}

__global__ void scan_pass2(const float* __restrict__ decay,
                           const float* __restrict__ fend, const float* __restrict__ bend,
                           float* __restrict__ fcar, float* __restrict__ bcar) {
    int c = threadIdx.x;
    float d = decay[c];
    float dS = d;
#pragma unroll
    for (int i = 0; i < 7; i++) dS = dS * dS;  // d^128
    float acc = 0.f;
#pragma unroll 4
    for (int k = 0; k < NCHUNK; k++) {
        fcar[k * CDIM + c] = acc;
        acc = fmaf(dS, acc, fend[k * CDIM + c]);
    }
    acc = 0.f;
#pragma unroll 4
    for (int k = NCHUNK - 1; k >= 0; k--) {
        bcar[k * CDIM + c] = acc;
        acc = fmaf(dS, acc, bend[k * CDIM + c]);
    }
}

// fwd sweep -> tmp (fp16); bwd sweep combines -> state (fp16, feeds W_out GEMM)
__global__ void scan_pass3(const __half* __restrict__ u, const __half* __restrict__ gate,
                           const float* __restrict__ decay,
                           const float* __restrict__ fcar, const float* __restrict__ bcar,
                           __half* __restrict__ tmp, __half* __restrict__ state) {
    int c = threadIdx.x;
    int ch = blockIdx.x;
    float d = decay[c];
    size_t off = (size_t)ch * SCH * CDIM + c;
    const __half* up = u + off;
    const __half* gp = gate + off;
    __half* tp = tmp + off;
    __half* sp = state + off;
    float acc = fcar[ch * CDIM + c];
#pragma unroll 8
    for (int r = 0; r < SCH; r++) {
        acc = fmaf(d, acc, __half2float(up[r * CDIM]));
        tp[r * CDIM] = __float2half(acc);
    }
    acc = bcar[ch * CDIM + c];
#pragma unroll 8
    for (int r = SCH - 1; r >= 0; r--) {
        acc = fmaf(d, acc, __half2float(up[r * CDIM]));
        float g = __half2float(gp[r * CDIM]);
        sp[r * CDIM] = __float2half(0.5f * (__half2float(tp[r * CDIM]) + acc) * g);
    }
}

// ---------------- launch ----------------
extern "C" void kernel_launch(void* const* d_in, const int* in_sizes, int n_in,
                              void* d_out, int out_size) {
    const float* x       = (const float*)d_in[0];
    const float* ln1_w   = (const float*)d_in[1];
    const float* ln1_b   = (const float*)d_in[2];
    const float* W_in    = (const float*)d_in[3];
    const float* b_in    = (const float*)d_in[4];
    const float* W_gate  = (const float*)d_in[5];
    const float* b_gate  = (const float*)d_in[6];
    const float* W_out   = (const float*)d_in[7];
    const float* b_out   = (const float*)d_in[8];
    const float* dlogit  = (const float*)d_in[9];
    const float* ln2_w   = (const float*)d_in[10];
    const float* ln2_b   = (const float*)d_in[11];
    const float* W_ff1   = (const float*)d_in[12];
    const float* b_ff1   = (const float*)d_in[13];
    const float* W_ff2   = (const float*)d_in[14];
    const float* b_ff2   = (const float*)d_in[15];
    float* out = (float*)d_out;

    __half *p_hidden, *p_u, *p_gate, *p_state, *p_h, *p_ff, *p_tmp, *p_wt;
    float *p_x2, *p_decay;
    float *p_fend, *p_bend, *p_fcar, *p_bcar;
    cudaGetSymbolAddress((void**)&p_hidden, g_hidden);
    cudaGetSymbolAddress((void**)&p_u, g_u);
    cudaGetSymbolAddress((void**)&p_gate, g_gate);
    cudaGetSymbolAddress((void**)&p_state, g_state);
    cudaGetSymbolAddress((void**)&p_x2, g_x2);
    cudaGetSymbolAddress((void**)&p_h, g_h);
    cudaGetSymbolAddress((void**)&p_ff, g_ff);
    cudaGetSymbolAddress((void**)&p_tmp, g_tmp);
    cudaGetSymbolAddress((void**)&p_decay, g_decay);
    cudaGetSymbolAddress((void**)&p_fend, g_fend);
    cudaGetSymbolAddress((void**)&p_bend, g_bend);
    cudaGetSymbolAddress((void**)&p_fcar, g_fcar);
    cudaGetSymbolAddress((void**)&p_bcar, g_bcar);
    cudaGetSymbolAddress((void**)&p_wt, g_wt);

    __half* wt_in   = p_wt;
    __half* wt_gate = p_wt + CDIM * CDIM;
    __half* wt_out  = p_wt + 2 * CDIM * CDIM;
    __half* wt_ff1  = p_wt + 3 * CDIM * CDIM;
    __half* wt_ff2  = p_wt + 3 * CDIM * CDIM + CDIM * 2 * CDIM;

    cudaFuncSetAttribute(gemm_kernel<0, false>, cudaFuncAttributeMaxDynamicSharedMemorySize, SMEM_TOTAL);
    cudaFuncSetAttribute(gemm_kernel<0, true>,  cudaFuncAttributeMaxDynamicSharedMemorySize, SMEM_TOTAL);
    cudaFuncSetAttribute(gemm_kernel<1, true>,  cudaFuncAttributeMaxDynamicSharedMemorySize, SMEM_TOTAL);
    cudaFuncSetAttribute(gemm_kernel<2, true>,  cudaFuncAttributeMaxDynamicSharedMemorySize, SMEM_TOTAL);

    dim3 lnBlock(32, 8);
    int lnGrid = LSEQ / 8;

    // launch #1: pack W_in|W_gate|W_out
    pack_w1<<<768, 256>>>(W_in, W_gate, W_out, p_wt);
    // launch #2: pack W_ff1|W_ff2 + decay
    pack_w2<<<1026, 256>>>(W_ff1, W_ff2, dlogit, wt_ff1, p_decay);

    // launch #3: hidden = fp16(LN1(x))
    ln_kernel<<<lnGrid, lnBlock>>>(x, ln1_w, ln1_b, p_hidden);

    // launches #4, #5: u / gate GEMMs  (#5 lands in the ncu capture slot)
    dim3 g512(CDIM / 256, LSEQ / 128);
    gemm_kernel<0, true><<<g512, GTHREADS, SMEM_TOTAL>>>(p_hidden, wt_in, b_in, nullptr, p_u, LSEQ, CDIM, CDIM);
    gemm_kernel<1, true><<<g512, GTHREADS, SMEM_TOTAL>>>(p_hidden, wt_gate, b_gate, nullptr, p_gate, LSEQ, CDIM, CDIM);

    // bidirectional scan -> state = fp16(0.5*(fwd+bwd)*gate)
    scan_pass1<<<NCHUNK, CDIM>>>(p_u, p_decay, p_fend, p_bend);
    scan_pass2<<<1, CDIM>>>(p_decay, p_fend, p_bend, p_fcar, p_bcar);
    scan_pass3<<<NCHUNK, CDIM>>>(p_u, p_gate, p_decay, p_fcar, p_bcar, p_tmp, p_state);

    // x2 = x + state @ W_out + b_out   (fp32 out)
    gemm_kernel<0, false><<<g512, GTHREADS, SMEM_TOTAL>>>(p_state, wt_out, b_out, x, p_x2, LSEQ, CDIM, CDIM);

    // h = fp16(LN2(x2))
    ln_kernel<<<lnGrid, lnBlock>>>(p_x2, ln2_w, ln2_b, p_h);

    // ff = fp16(silu(h @ W_ff1 + b_ff1))  [N = 1024]
    dim3 g1024(2 * CDIM / 256, LSEQ / 128);
    gemm_kernel<2, true><<<g1024, GTHREADS, SMEM_TOTAL>>>(p_h, wt_ff1, b_ff1, nullptr, p_ff, LSEQ, 2 * CDIM, CDIM);

    // out = x2 + ff @ W_ff2 + b_ff2  [K = 1024, fp32 out]
    gemm_kernel<0, false><<<g512, GTHREADS, SMEM_TOTAL>>>(p_ff, wt_ff2, b_ff2, p_x2, out, LSEQ, CDIM, 2 * CDIM);
}

// round 15
// speedup vs baseline: 1.1747x; 1.1747x over previous
#include <cuda_runtime.h>
#include <cuda_fp16.h>
#include <mma.h>
#include <math.h>
#include <cstdint>

using namespace nvcuda;

#define LSEQ 32768
#define CDIM 512
#define SCH 128
#define NCHUNK (LSEQ / SCH)   // 256
#define EPS 1e-5f

// GEMM tiling: block 128x128, 8 warps (256 thr), warp tile 64x32, BK=64, fp16, 3 stages, 2 CTA/SM
#define GTHREADS 256
#define NSTAGE 3
#define AS_STRIDE 72            // 64 + 8 pad -> 144B rows (odd multiple of 16B: conflict-free)
#define BS_STRIDE 136           // 128 + 8 pad -> 272B rows (odd multiple of 16B)
#define EP_STRIDE 132
#define A_BYTES (128 * AS_STRIDE * 2)          // 18432
#define B_BYTES (64 * BS_STRIDE * 2)           // 17408
#define STG_BYTES (A_BYTES + B_BYTES)          // 35840
#define SMEM_TOTAL (NSTAGE * STG_BYTES)        // 107520 (>= 128*132*4 = 67584 epilogue; 2 CTAs fit 228KB)

// ---------------- scratch (static device globals; no allocation) ----------------
__device__ __half g_hidden[LSEQ * CDIM];
__device__ __half g_u[LSEQ * CDIM];
__device__ __half g_gate[LSEQ * CDIM];
__device__ __half g_state[LSEQ * CDIM];
__device__ float  g_x2[LSEQ * CDIM];
__device__ __half g_h[LSEQ * CDIM];
__device__ __half g_ff[LSEQ * 2 * CDIM];
__device__ __half g_tmp[LSEQ * CDIM];     // fwd-scan scratch (fp16)
__device__ float  g_decay[CDIM];
__device__ float  g_fend[NCHUNK * CDIM];
__device__ float  g_bend[NCHUNK * CDIM];
__device__ float  g_fcar[NCHUNK * CDIM];
__device__ float  g_bcar[NCHUNK * CDIM];
// fp16 weight copies: W_in | W_gate | W_out | W_ff1 | W_ff2
__device__ __half g_wt[3 * CDIM * CDIM + 2 * CDIM * 2 * CDIM];

__device__ __forceinline__ uint32_t smem_u32(const void* p) {
    uint32_t a;
    asm("{ .reg .u64 t; cvta.to.shared.u64 t, %1; cvt.u32.u64 %0, t; }" : "=r"(a) : "l"(p));
    return a;
}

#define CP_ASYNC16(dst_u32, gptr) \
    asm volatile("cp.async.cg.shared.global [%0], [%1], 16;" :: "r"(dst_u32), "l"(gptr))
#define CP_COMMIT() asm volatile("cp.async.commit_group;" ::: "memory")
#define CP_WAIT(n)  asm volatile("cp.async.wait_group %0;" :: "n"(n) : "memory")

// ---------------- weight packing (2 launches total) ----------------
__global__ void pack_w1(const float* __restrict__ Win, const float* __restrict__ Wgate,
                        const float* __restrict__ Wout, __half* __restrict__ wt) {
    int i = blockIdx.x * blockDim.x + threadIdx.x;     // 0..196607 float4 units
    int seg = i >> 16;
    int o = i & 65535;
    const float* src = (seg == 0) ? Win : (seg == 1) ? Wgate : Wout;
    float4 v = ((const float4*)src)[o];
    __half2* d2 = (__half2*)wt + (size_t)i * 2;
    d2[0] = __floats2half2_rn(v.x, v.y);
    d2[1] = __floats2half2_rn(v.z, v.w);
}

__global__ void pack_w2(const float* __restrict__ Wff1, const float* __restrict__ Wff2,
                        const float* __restrict__ logit,
                        __half* __restrict__ wt2, float* __restrict__ decay) {
    int i = blockIdx.x * blockDim.x + threadIdx.x;
    if (i < 262144) {
        const float* src = (i < 131072) ? Wff1 : Wff2;
        int o = (i < 131072) ? i : i - 131072;
        float4 v = ((const float4*)src)[o];
        __half2* d2 = (__half2*)wt2 + (size_t)i * 2;
        d2[0] = __floats2half2_rn(v.x, v.y);
        d2[1] = __floats2half2_rn(v.z, v.w);
    } else {
        int j = i - 262144;
        if (j < CDIM) decay[j] = 1.0f / (1.0f + expf(-logit[j]));
    }
}

// ---------------- LayerNorm: one warp per row; fp16 output ----------------
__global__ void ln_kernel(const float* __restrict__ x, const float* __restrict__ w,
                          const float* __restrict__ b, __half* __restrict__ out) {
    int row = blockIdx.x * blockDim.y + threadIdx.y;
    int lane = threadIdx.x;
    const float4* xr = (const float4*)(x + (size_t)row * CDIM);
    float4 v[4];
    float s = 0.f, ss = 0.f;
#pragma unroll
    for (int i = 0; i < 4; i++) {
        v[i] = xr[lane + i * 32];
        s += v[i].x + v[i].y + v[i].z + v[i].w;
        ss += v[i].x * v[i].x + v[i].y * v[i].y + v[i].z * v[i].z + v[i].w * v[i].w;
    }
#pragma unroll
    for (int off = 16; off > 0; off >>= 1) {
        s += __shfl_xor_sync(0xFFFFFFFFu, s, off);
        ss += __shfl_xor_sync(0xFFFFFFFFu, ss, off);
    }
    float mu = s * (1.0f / CDIM);
    float var = ss * (1.0f / CDIM) - mu * mu;
    float rstd = rsqrtf(var + EPS);
    const float4* w4 = (const float4*)w;
    const float4* b4 = (const float4*)b;
    __half2* o2 = (__half2*)(out + (size_t)row * CDIM);
#pragma unroll
    for (int i = 0; i < 4; i++) {
        int idx = lane + i * 32;
        float4 wv = w4[idx], bv = b4[idx];
        float ox = (v[i].x - mu) * rstd * wv.x + bv.x;
        float oy = (v[i].y - mu) * rstd * wv.y + bv.y;
        float oz = (v[i].z - mu) * rstd * wv.z + bv.z;
        float ow = (v[i].w - mu) * rstd * wv.w + bv.w;
        o2[idx * 2]     = __floats2half2_rn(ox, oy);
        o2[idx * 2 + 1] = __floats2half2_rn(oz, ow);
    }
}

// ---------------- fp16 wmma GEMM 128x128, 8 warps (64x32 tiles), BK=64, 3-stage, 2 CTA/SM ----
// A: MxK fp16 row-major, B: KxN fp16 row-major. C = epi(A@B + bias) [+ res].
// EPI: 0 = identity, 1 = sigmoid, 2 = silu.  OH16: output fp16 (else fp32).
template <int EPI, bool OH16>
__global__ void __launch_bounds__(GTHREADS, 2)
gemm_kernel(const __half* __restrict__ A, const __half* __restrict__ B,
            const float* __restrict__ bias, const float* __restrict__ res,
            void* __restrict__ Cout, int M, int N, int K) {
    extern __shared__ char smem[];
    uint32_t sb = smem_u32(smem);

    int tid = threadIdx.x;
    int w = tid >> 5;
    int wr = w & 1;        // 0..1  -> 64-row slab
    int wc = w >> 1;       // 0..3  -> 32-col slab
    int rowBase = blockIdx.y * 128;
    int nBase = blockIdx.x * 128;

    wmma::fragment<wmma::accumulator, 16, 16, 16, float> acc[4][2];
#pragma unroll
    for (int i = 0; i < 4; i++)
#pragma unroll
        for (int j = 0; j < 2; j++) wmma::fill_fragment(acc[i][j], 0.0f);

    const int T = K >> 6;   // BK = 64

    // A tile 128x64 fp16 (stride 72), B tile 64x128 fp16 (stride 136)
    auto load_stage = [&](int t, int s) {
        int k0 = t << 6;
        uint32_t abase = sb + s * STG_BYTES;
        uint32_t bbase = abase + A_BYTES;
#pragma unroll
        for (int p = 0; p < 4; p++) {
            int idx = tid + GTHREADS * p;      // 1024 chunks of 8 fp16
            int row = idx >> 3;
            int c8 = (idx & 7) * 8;
            CP_ASYNC16(abase + (uint32_t)(row * AS_STRIDE + c8) * 2,
                       A + (size_t)(rowBase + row) * K + k0 + c8);
        }
#pragma unroll
        for (int p = 0; p < 4; p++) {
            int idx = tid + GTHREADS * p;      // 1024 chunks (64 rows x 16)
            int kr = idx >> 4;
            int c8 = (idx & 15) * 8;
            CP_ASYNC16(bbase + (uint32_t)(kr * BS_STRIDE + c8) * 2,
                       B + (size_t)(k0 + kr) * N + nBase + c8);
        }
    };

    // prologue: stages 0, 1
#pragma unroll
    for (int s = 0; s < NSTAGE - 1; s++) {
        load_stage(s, s);
        CP_COMMIT();
    }

    for (int t = 0; t < T; t++) {
        CP_WAIT(NSTAGE - 2);
        __syncthreads();
        // slot (t+2)%3 == (t-1)%3: sync above proves all warps finished compute t-1
        if (t + NSTAGE - 1 < T) load_stage(t + NSTAGE - 1, (t + NSTAGE - 1) % NSTAGE);
        CP_COMMIT();   // unconditional: exact group accounting

        int s = t % NSTAGE;
        const __half* As = (const __half*)(smem + s * STG_BYTES);
        const __half* Bs = (const __half*)(smem + s * STG_BYTES + A_BYTES);
#pragma unroll
        for (int kk = 0; kk < 4; kk++) {
            wmma::fragment<wmma::matrix_a, 16, 16, 16, __half, wmma::row_major> a[4];
            wmma::fragment<wmma::matrix_b, 16, 16, 16, __half, wmma::row_major> bfr[2];
#pragma unroll
            for (int i = 0; i < 4; i++)
                wmma::load_matrix_sync(a[i], As + (wr * 64 + i * 16) * AS_STRIDE + kk * 16, AS_STRIDE);
#pragma unroll
            for (int j = 0; j < 2; j++)
                wmma::load_matrix_sync(bfr[j], Bs + (kk * 16) * BS_STRIDE + wc * 32 + j * 16, BS_STRIDE);
#pragma unroll
            for (int i = 0; i < 4; i++)
#pragma unroll
                for (int j = 0; j < 2; j++)
                    wmma::mma_sync(acc[i][j], a[i], bfr[j], acc[i][j]);
        }
    }
    __syncthreads();   // all compute done before smem reuse

    // ---- epilogue: single 128x128 tile via reused smem staging ----
    float* ep = (float*)smem;
#pragma unroll
    for (int i = 0; i < 4; i++)
#pragma unroll
        for (int j = 0; j < 2; j++)
            wmma::store_matrix_sync(ep + (size_t)(wr * 64 + i * 16) * EP_STRIDE + wc * 32 + j * 16,
                                    acc[i][j], EP_STRIDE, wmma::mem_row_major);
    __syncthreads();

#pragma unroll
    for (int p = 0; p < 16; p++) {
        int idx = tid + GTHREADS * p;     // 4096 float4 = 128 rows x 32 float4
        int row = idx >> 5;
        int c4 = (idx & 31) * 4;
        float4 v = *(float4*)(ep + (size_t)row * EP_STRIDE + c4);
        float4 bv = *(const float4*)(bias + nBase + c4);
        v.x += bv.x; v.y += bv.y; v.z += bv.z; v.w += bv.w;
        if (EPI == 1) {
            v.x = 1.0f / (1.0f + expf(-v.x)); v.y = 1.0f / (1.0f + expf(-v.y));
            v.z = 1.0f / (1.0f + expf(-v.z)); v.w = 1.0f / (1.0f + expf(-v.w));
        }
        if (EPI == 2) {
            v.x = v.x / (1.0f + expf(-v.x)); v.y = v.y / (1.0f + expf(-v.y));
            v.z = v.z / (1.0f + expf(-v.z)); v.w = v.w / (1.0f + expf(-v.w));
        }
        size_t goff = (size_t)(rowBase + row) * N + nBase + c4;
        if (res) {
            float4 rv = *(const float4*)(res + goff);
            v.x += rv.x; v.y += rv.y; v.z += rv.z; v.w += rv.w;
        }
        if (OH16) {
            __half2* op = (__half2*)((__half*)Cout + goff);
            op[0] = __floats2half2_rn(v.x, v.y);
            op[1] = __floats2half2_rn(v.z, v.w);
        } else {
            *(float4*)((float*)Cout + goff) = v;
        }
    }
}

// ---------------- chunked bidirectional scan (fp16 inputs, fp32 accumulation) ----------------
__global__ void scan_pass1(const __half* __restrict__ u, const float* __restrict__ decay,
                           float* __restrict__ fend, float* __restrict__ bend) {
    int c = threadIdx.x;
    int ch = blockIdx.x;
    float d = decay[c];
    const __half* up = u + (size_t)ch * SCH * CDIM + c;
    float acc = 0.f;
#pragma unroll 8
    for (int r = 0; r < SCH; r++) acc = fmaf(d, acc, __half2float(up[r * CDIM]));
    fend[ch * CDIM + c] = acc;
    acc = 0.f;
#pragma unroll 8
    for (int r = SCH - 1; r >= 0; r--) acc = fmaf(d, acc, __half2float(up[r * CDIM]));
    bend[ch * CDIM + c] = acc;
}

__global__ void scan_pass2(const float* __restrict__ decay,
                           const float* __restrict__ fend, const float* __restrict__ bend,
                           float* __restrict__ fcar, float* __restrict__ bcar) {
    int c = threadIdx.x;
    float d = decay[c];
    float dS = d;
#pragma unroll
    for (int i = 0; i < 7; i++) dS = dS * dS;  // d^128
    float acc = 0.f;
#pragma unroll 4
    for (int k = 0; k < NCHUNK; k++) {
        fcar[k * CDIM + c] = acc;
        acc = fmaf(dS, acc, fend[k * CDIM + c]);
    }
    acc = 0.f;
#pragma unroll 4
    for (int k = NCHUNK - 1; k >= 0; k--) {
        bcar[k * CDIM + c] = acc;
        acc = fmaf(dS, acc, bend[k * CDIM + c]);
    }
}

// fwd sweep -> tmp (fp16); bwd sweep combines -> state (fp16, feeds W_out GEMM)
__global__ void scan_pass3(const __half* __restrict__ u, const __half* __restrict__ gate,
                           const float* __restrict__ decay,
                           const float* __restrict__ fcar, const float* __restrict__ bcar,
                           __half* __restrict__ tmp, __half* __restrict__ state) {
    int c = threadIdx.x;
    int ch = blockIdx.x;
    float d = decay[c];
    size_t off = (size_t)ch * SCH * CDIM + c;
    const __half* up = u + off;
    const __half* gp = gate + off;
    __half* tp = tmp + off;
    __half* sp = state + off;
    float acc = fcar[ch * CDIM + c];
#pragma unroll 8
    for (int r = 0; r < SCH; r++) {
        acc = fmaf(d, acc, __half2float(up[r * CDIM]));
        tp[r * CDIM] = __float2half(acc);
    }
    acc = bcar[ch * CDIM + c];
#pragma unroll 8
    for (int r = SCH - 1; r >= 0; r--) {
        acc = fmaf(d, acc, __half2float(up[r * CDIM]));
        float g = __half2float(gp[r * CDIM]);
        sp[r * CDIM] = __float2half(0.5f * (__half2float(tp[r * CDIM]) + acc) * g);
    }
}

// ---------------- launch ----------------
extern "C" void kernel_launch(void* const* d_in, const int* in_sizes, int n_in,
                              void* d_out, int out_size) {
    const float* x       = (const float*)d_in[0];
    const float* ln1_w   = (const float*)d_in[1];
    const float* ln1_b   = (const float*)d_in[2];
    const float* W_in    = (const float*)d_in[3];
    const float* b_in    = (const float*)d_in[4];
    const float* W_gate  = (const float*)d_in[5];
    const float* b_gate  = (const float*)d_in[6];
    const float* W_out   = (const float*)d_in[7];
    const float* b_out   = (const float*)d_in[8];
    const float* dlogit  = (const float*)d_in[9];
    const float* ln2_w   = (const float*)d_in[10];
    const float* ln2_b   = (const float*)d_in[11];
    const float* W_ff1   = (const float*)d_in[12];
    const float* b_ff1   = (const float*)d_in[13];
    const float* W_ff2   = (const float*)d_in[14];
    const float* b_ff2   = (const float*)d_in[15];
    float* out = (float*)d_out;

    __half *p_hidden, *p_u, *p_gate, *p_state, *p_h, *p_ff, *p_tmp, *p_wt;
    float *p_x2, *p_decay;
    float *p_fend, *p_bend, *p_fcar, *p_bcar;
    cudaGetSymbolAddress((void**)&p_hidden, g_hidden);
    cudaGetSymbolAddress((void**)&p_u, g_u);
    cudaGetSymbolAddress((void**)&p_gate, g_gate);
    cudaGetSymbolAddress((void**)&p_state, g_state);
    cudaGetSymbolAddress((void**)&p_x2, g_x2);
    cudaGetSymbolAddress((void**)&p_h, g_h);
    cudaGetSymbolAddress((void**)&p_ff, g_ff);
    cudaGetSymbolAddress((void**)&p_tmp, g_tmp);
    cudaGetSymbolAddress((void**)&p_decay, g_decay);
    cudaGetSymbolAddress((void**)&p_fend, g_fend);
    cudaGetSymbolAddress((void**)&p_bend, g_bend);
    cudaGetSymbolAddress((void**)&p_fcar, g_fcar);
    cudaGetSymbolAddress((void**)&p_bcar, g_bcar);
    cudaGetSymbolAddress((void**)&p_wt, g_wt);

    __half* wt_in   = p_wt;
    __half* wt_gate = p_wt + CDIM * CDIM;
    __half* wt_out  = p_wt + 2 * CDIM * CDIM;
    __half* wt_ff1  = p_wt + 3 * CDIM * CDIM;
    __half* wt_ff2  = p_wt + 3 * CDIM * CDIM + CDIM * 2 * CDIM;

    cudaFuncSetAttribute(gemm_kernel<0, false>, cudaFuncAttributeMaxDynamicSharedMemorySize, SMEM_TOTAL);
    cudaFuncSetAttribute(gemm_kernel<0, true>,  cudaFuncAttributeMaxDynamicSharedMemorySize, SMEM_TOTAL);
    cudaFuncSetAttribute(gemm_kernel<1, true>,  cudaFuncAttributeMaxDynamicSharedMemorySize, SMEM_TOTAL);
    cudaFuncSetAttribute(gemm_kernel<2, true>,  cudaFuncAttributeMaxDynamicSharedMemorySize, SMEM_TOTAL);

    dim3 lnBlock(32, 8);
    int lnGrid = LSEQ / 8;

    // launch #1: pack W_in|W_gate|W_out
    pack_w1<<<768, 256>>>(W_in, W_gate, W_out, p_wt);
    // launch #2: pack W_ff1|W_ff2 + decay
    pack_w2<<<1026, 256>>>(W_ff1, W_ff2, dlogit, wt_ff1, p_decay);

    // launch #3: hidden = fp16(LN1(x))
    ln_kernel<<<lnGrid, lnBlock>>>(x, ln1_w, ln1_b, p_hidden);

    // launches #4, #5: u / gate GEMMs  (#5 lands in the ncu capture slot)
    dim3 g512(CDIM / 128, LSEQ / 128);
    gemm_kernel<0, true><<<g512, GTHREADS, SMEM_TOTAL>>>(p_hidden, wt_in, b_in, nullptr, p_u, LSEQ, CDIM, CDIM);
    gemm_kernel<1, true><<<g512, GTHREADS, SMEM_TOTAL>>>(p_hidden, wt_gate, b_gate, nullptr, p_gate, LSEQ, CDIM, CDIM);

    // bidirectional scan -> state = fp16(0.5*(fwd+bwd)*gate)
    scan_pass1<<<NCHUNK, CDIM>>>(p_u, p_decay, p_fend, p_bend);
    scan_pass2<<<1, CDIM>>>(p_decay, p_fend, p_bend, p_fcar, p_bcar);
    scan_pass3<<<NCHUNK, CDIM>>>(p_u, p_gate, p_decay, p_fcar, p_bcar, p_tmp, p_state);

    // x2 = x + state @ W_out + b_out   (fp32 out)
    gemm_kernel<0, false><<<g512, GTHREADS, SMEM_TOTAL>>>(p_state, wt_out, b_out, x, p_x2, LSEQ, CDIM, CDIM);

    // h = fp16(LN2(x2))
    ln_kernel<<<lnGrid, lnBlock>>>(p_x2, ln2_w, ln2_b, p_h);

    // ff = fp16(silu(h @ W_ff1 + b_ff1))  [N = 1024]
    dim3 g1024(2 * CDIM / 128, LSEQ / 128);
    gemm_kernel<2, true><<<g1024, GTHREADS, SMEM_TOTAL>>>(p_h, wt_ff1, b_ff1, nullptr, p_ff, LSEQ, 2 * CDIM, CDIM);

    // out = x2 + ff @ W_ff2 + b_ff2  [K = 1024, fp32 out]
    gemm_kernel<0, false><<<g512, GTHREADS, SMEM_TOTAL>>>(p_ff, wt_ff2, b_ff2, p_x2, out, LSEQ, CDIM, 2 * CDIM);
}